// round 13
// baseline (speedup 1.0000x reference)
#include <cuda_runtime.h>
#include <cuda_bf16.h>

// ----------------------------------------------------------------------------
// SplineCoupling fused kernel, round 13: R12 resubmit (infra failure retry).
// GEMM3 on mma.sync.m16n8k16 bf16 (2-term split, merged k-loop), 16 GEMM
// warps, phases 1-2 FFMA. Per CTA: 128 rows, 512 threads, ~203KB smem.
// ----------------------------------------------------------------------------

namespace {
constexpr int kB       = 262144;
constexpr int kThreads = 512;

// byte offsets in dynamic smem
constexpr int XU_B  = 0;        // 16896 : xu -> yu (128*33 f32)
constexpr int BP_B  = 16896;    // 3200  : bp
constexpr int BV_B  = 20096;    // 3072  : b0,g0,be0,b1,g1,be1
constexpr int AHI_B = 23296;    // 34816 : A_hi bf16 [m][k] stride 136 (272B)
constexpr int ALO_B = 58112;    // 34816 : A_lo
constexpr int BHI_B = 92928;    // 30720 : B_hi bf16 [k][n] stride 120 (240B)
constexpr int BLO_B = 123648;   // 30720 : B_lo
constexpr int RAW_B = 154368;   // 53760 : raw logits f32 [row][105]
constexpr int SMEM_BYTES = 208128;
// phase 1-2 overlays
constexpr int W_B = AHI_B;      // W0 (16KB) then W1 (64KB) fp32
constexpr int H_B = BHI_B;      // xm (row*33) then H1 (row*129) fp32
}  // namespace

__device__ __forceinline__ void cp_async16(unsigned dst, const float4* src) {
    asm volatile("cp.async.cg.shared.global [%0], [%1], 16;" :: "r"(dst), "l"(src));
}
__device__ __forceinline__ void cp_commit() { asm volatile("cp.async.commit_group;"); }
__device__ __forceinline__ void cp_wait0()  { asm volatile("cp.async.wait_group 0;"); }

__device__ __forceinline__ void ldsm_x4(unsigned addr, unsigned& r0, unsigned& r1,
                                        unsigned& r2, unsigned& r3) {
    asm volatile("ldmatrix.sync.aligned.m8n8.x4.shared.b16 {%0,%1,%2,%3}, [%4];"
                 : "=r"(r0), "=r"(r1), "=r"(r2), "=r"(r3) : "r"(addr));
}
__device__ __forceinline__ void ldsm_x2t(unsigned addr, unsigned& r0, unsigned& r1) {
    asm volatile("ldmatrix.sync.aligned.m8n8.x2.trans.shared.b16 {%0,%1}, [%2];"
                 : "=r"(r0), "=r"(r1) : "r"(addr));
}
__device__ __forceinline__ void mma16816(float* d, const unsigned* a,
                                         unsigned b0, unsigned b1) {
    asm volatile(
        "mma.sync.aligned.m16n8k16.row.col.f32.bf16.bf16.f32 "
        "{%0,%1,%2,%3}, {%4,%5,%6,%7}, {%8,%9}, {%0,%1,%2,%3};"
        : "+f"(d[0]), "+f"(d[1]), "+f"(d[2]), "+f"(d[3])
        : "r"(a[0]), "r"(a[1]), "r"(a[2]), "r"(a[3]), "r"(b0), "r"(b1));
}
__device__ __forceinline__ unsigned pack_bf2(__nv_bfloat16 a, __nv_bfloat16 b) {
    return ((unsigned)__bfloat16_as_ushort(b) << 16) | __bfloat16_as_ushort(a);
}

// RQS spline epilogue for one (row, dim): proven numerics from R6/R8/R11.
__device__ __forceinline__ float rqs_epilogue(const float* __restrict__ rawp,
                                              const float* __restrict__ bpd,
                                              float* __restrict__ xuslot)
{
    float wr[8], hr[8], dr9[9];
    #pragma unroll
    for (int j = 0; j < 8; j++) wr[j] = rawp[j] + bpd[j];
    #pragma unroll
    for (int j = 0; j < 8; j++) hr[j] = rawp[8 + j] + bpd[8 + j];
    #pragma unroll
    for (int j = 0; j < 9; j++) dr9[j] = rawp[16 + j] + bpd[16 + j];

    float mw = wr[0];
    #pragma unroll
    for (int j = 1; j < 8; j++) mw = fmaxf(mw, wr[j]);
    float ew[8], sw = 0.f;
    #pragma unroll
    for (int j = 0; j < 8; j++) { ew[j] = __expf(wr[j] - mw); sw += ew[j]; }
    float scw = 5.952f / sw;
    float w[8];
    #pragma unroll
    for (int j = 0; j < 8; j++) w[j] = 0.006f + ew[j] * scw;

    float mh = hr[0];
    #pragma unroll
    for (int j = 1; j < 8; j++) mh = fmaxf(mh, hr[j]);
    float eh[8], shs = 0.f;
    #pragma unroll
    for (int j = 0; j < 8; j++) { eh[j] = __expf(hr[j] - mh); shs += eh[j]; }
    float sch = 5.952f / shs;
    float h[8];
    #pragma unroll
    for (int j = 0; j < 8; j++) h[j] = 0.006f + eh[j] * sch;

    float dv[9];
    #pragma unroll
    for (int j = 0; j < 9; j++) {
        float xx = dr9[j];
        dv[j] = fmaxf(xx, 0.f) + __logf(1.f + __expf(-fabsf(xx))) + 0.001f;
    }

    float xu = *xuslot;
    bool inside = (xu > -3.f) && (xu < 3.f);
    float xc = fminf(fmaxf(xu, -3.f), 3.f);

    float cwv[9], chv[9];
    cwv[0] = -3.f; chv[0] = -3.f;
    #pragma unroll
    for (int j = 0; j < 8; j++) {
        cwv[j + 1] = cwv[j] + w[j];
        chv[j + 1] = chv[j] + h[j];
    }
    int idx = 0;
    #pragma unroll
    for (int j = 1; j <= 8; j++) idx += (xc >= cwv[j]) ? 1 : 0;
    idx = min(idx, 7);

    float w_k = w[0], x_k = cwv[0], h_k = h[0], y_k = chv[0];
    float d_k = dv[0], d_k1 = dv[1];
    #pragma unroll
    for (int j = 1; j < 8; j++) {
        if (idx == j) {
            w_k = w[j]; x_k = cwv[j]; h_k = h[j]; y_k = chv[j];
            d_k = dv[j]; d_k1 = dv[j + 1];
        }
    }
    float s   = h_k / w_k;
    float th  = (xc - x_k) / w_k;
    float om  = 1.f - th;
    float t1m = th * om;
    float den = s + (d_k1 + d_k - 2.f * s) * t1m;
    float yin = y_k + h_k * (s * th * th + d_k * t1m) / den;
    float num = d_k1 * th * th + 2.f * s * t1m + d_k * om * om;
    float ldin = 2.f * __logf(s) + __logf(num) - 2.f * __logf(den);

    *xuslot = inside ? yin : xu;
    return inside ? ldin : 0.f;
}

__global__ void __launch_bounds__(512, 1) spline_fused_kernel(
    const float* __restrict__ x,
    const float* __restrict__ W0, const float* __restrict__ b0,
    const float* __restrict__ g0, const float* __restrict__ be0,
    const float* __restrict__ W1, const float* __restrict__ b1,
    const float* __restrict__ g1, const float* __restrict__ be1,
    const float* __restrict__ Wp, const float* __restrict__ bp,
    float* __restrict__ out)
{
    extern __shared__ char smc[];
    float* sXU  = reinterpret_cast<float*>(smc + XU_B);
    float* sBP  = reinterpret_cast<float*>(smc + BP_B);
    float* sBV  = reinterpret_cast<float*>(smc + BV_B);
    float* sW   = reinterpret_cast<float*>(smc + W_B);   // W0 -> W1 (fp32)
    float* sH   = reinterpret_cast<float*>(smc + H_B);   // xm -> H1 (fp32)
    float* sRaw = reinterpret_cast<float*>(smc + RAW_B);
    const unsigned smem_u32 = (unsigned)__cvta_generic_to_shared(smc);

    const int tid  = threadIdx.x;
    const int wid  = tid >> 5;
    const int lane = tid & 31;
    const int r0   = blockIdx.x * 128;

    // ---------------- cooperative loads ----------------
    {
        const float4* xg = reinterpret_cast<const float4*>(x + (size_t)r0 * 64);
        #pragma unroll
        for (int i = tid; i < 128 * 16; i += kThreads) {
            int r = i >> 4, v = i & 15;
            float4 f = xg[i];
            sH [r * 33 + 2 * v]     = f.x;   // xm
            sXU[r * 33 + 2 * v]     = f.y;
            sH [r * 33 + 2 * v + 1] = f.z;
            sXU[r * 33 + 2 * v + 1] = f.w;
        }
        const float4* w0g = reinterpret_cast<const float4*>(W0);
        #pragma unroll
        for (int i = tid; i < 1024; i += kThreads)
            reinterpret_cast<float4*>(sW)[i] = w0g[i];
        const float4* bpg = reinterpret_cast<const float4*>(bp);
        #pragma unroll
        for (int i = tid; i < 200; i += kThreads)
            reinterpret_cast<float4*>(sBP)[i] = bpg[i];
        if (tid < 128) {
            sBV[tid]       = b0[tid];
            sBV[128 + tid] = g0[tid];
            sBV[256 + tid] = be0[tid];
            sBV[384 + tid] = b1[tid];
            sBV[512 + tid] = g1[tid];
            sBV[640 + tid] = be1[tid];
        }
    }
    __syncthreads();

    // ---------------- Phase 1: GEMM1 (K=32) tile 4x8 ----------------
    {
        const int rg = tid >> 4, cg = tid & 15;
        float acc1[4][8];
        #pragma unroll
        for (int r = 0; r < 4; r++)
            #pragma unroll
            for (int i = 0; i < 8; i++) acc1[r][i] = 0.f;

        #pragma unroll 4
        for (int k = 0; k < 32; k++) {
            float a[4];
            #pragma unroll
            for (int r = 0; r < 4; r++) a[r] = sH[(rg * 4 + r) * 33 + k];
            #pragma unroll
            for (int i = 0; i < 8; i++) {
                float b = sW[k * 128 + cg + 16 * i];
                #pragma unroll
                for (int r = 0; r < 4; r++) acc1[r][i] += a[r] * b;
            }
        }
        __syncthreads();   // xm & W0 reads done

        {   // kick W1 into sW via cp.async
            const float4* w1g = reinterpret_cast<const float4*>(W1);
            #pragma unroll
            for (int i = tid; i < 4096; i += kThreads)
                cp_async16(smem_u32 + (unsigned)(W_B + i * 16), w1g + i);
            cp_commit();
        }

        float mu[4], rs[4];
        #pragma unroll
        for (int r = 0; r < 4; r++) {
            float s1 = 0.f, s2 = 0.f;
            #pragma unroll
            for (int i = 0; i < 8; i++) {
                float v = acc1[r][i] + sBV[cg + 16 * i];
                acc1[r][i] = v;
                s1 += v; s2 += v * v;
            }
            #pragma unroll
            for (int d = 1; d < 16; d <<= 1) {
                s1 += __shfl_xor_sync(0xffffffffu, s1, d);
                s2 += __shfl_xor_sync(0xffffffffu, s2, d);
            }
            mu[r] = s1 * (1.f / 128.f);
            rs[r] = rsqrtf(s2 * (1.f / 128.f) - mu[r] * mu[r] + 1e-6f);
        }
        #pragma unroll
        for (int i = 0; i < 8; i++) {
            int c = cg + 16 * i;
            float gg = sBV[128 + c], bb = sBV[256 + c];
            #pragma unroll
            for (int r = 0; r < 4; r++) {
                float h = (acc1[r][i] - mu[r]) * rs[r] * gg + bb;
                sH[(rg * 4 + r) * 129 + c] = fmaxf(h, 0.f);   // H1
            }
        }
    }
    cp_wait0();
    __syncthreads();

    // ---------------- Phase 2: GEMM2 (K=128) tile 8x8, 256 threads ---------
    {
        const bool p2  = tid < 256;
        const int rg2  = tid >> 4;
        const int cg2  = tid & 15;
        float a2[8][8];
        if (p2) {
            #pragma unroll
            for (int r = 0; r < 8; r++)
                #pragma unroll
                for (int j = 0; j < 8; j++) a2[r][j] = 0.f;

            #pragma unroll 2
            for (int k = 0; k < 128; k++) {
                float bv_[8];
                #pragma unroll
                for (int j = 0; j < 8; j++) bv_[j] = sW[k * 128 + 16 * j + cg2];
                #pragma unroll
                for (int r = 0; r < 8; r++) {
                    float av = sH[(rg2 * 8 + r) * 129 + k];
                    #pragma unroll
                    for (int j = 0; j < 8; j++) a2[r][j] += av * bv_[j];
                }
            }
            #pragma unroll
            for (int r = 0; r < 8; r++) {
                float s1 = 0.f, s2 = 0.f;
                #pragma unroll
                for (int j = 0; j < 8; j++) {
                    float v = a2[r][j] + sBV[384 + 16 * j + cg2];
                    a2[r][j] = v;
                    s1 += v; s2 += v * v;
                }
                #pragma unroll
                for (int d = 1; d < 16; d <<= 1) {
                    s1 += __shfl_xor_sync(0xffffffffu, s1, d);
                    s2 += __shfl_xor_sync(0xffffffffu, s2, d);
                }
                float mu = s1 * (1.f / 128.f);
                float rs = rsqrtf(s2 * (1.f / 128.f) - mu * mu + 1e-6f);
                #pragma unroll
                for (int j = 0; j < 8; j++) {
                    int c = 16 * j + cg2;
                    float h = fmaxf((a2[r][j] - mu) * rs * sBV[512 + c] + sBV[640 + c], 0.f)
                              + sH[(rg2 * 8 + r) * 129 + c];    // residual
                    a2[r][j] = h;
                }
            }
        }
        __syncthreads();   // all W1 + H1 reads complete (uniform barrier)
        if (p2) {
            // H2 -> A_hi/A_lo bf16, [m][k] row-major stride 136
            #pragma unroll
            for (int r = 0; r < 8; r++) {
                int m = rg2 * 8 + r;
                #pragma unroll
                for (int j = 0; j < 8; j++) {
                    int k = 16 * j + cg2;
                    float v = a2[r][j];
                    __nv_bfloat16 hi = __float2bfloat16(v);
                    __nv_bfloat16 lo = __float2bfloat16(v - __bfloat162float(hi));
                    *reinterpret_cast<unsigned short*>(smc + AHI_B + m * 272 + k * 2) =
                        __bfloat16_as_ushort(hi);
                    *reinterpret_cast<unsigned short*>(smc + ALO_B + m * 272 + k * 2) =
                        __bfloat16_as_ushort(lo);
                }
            }
        }
        // zero B pad cols 100..103 for all 128 k rows (512 threads = 128*4)
        {
            int k = tid >> 2, n = 100 + (tid & 3);
            *reinterpret_cast<unsigned short*>(smc + BHI_B + k * 240 + n * 2) = 0;
            *reinterpret_cast<unsigned short*>(smc + BLO_B + k * 240 + n * 2) = 0;
        }
    }

    // ---------------- Phase 3: 8 chunks of 100 cols, mma.sync --------------
    auto stage_b = [&](int c) {
        const float* src = Wp + c * 100;
        for (int i = tid; i < 3200; i += kThreads) {
            int k = i / 25, n4 = i - k * 25;
            float4 v = *reinterpret_cast<const float4*>(src + k * 800 + n4 * 4);
            __nv_bfloat16 h0 = __float2bfloat16(v.x);
            __nv_bfloat16 h1 = __float2bfloat16(v.y);
            __nv_bfloat16 h2 = __float2bfloat16(v.z);
            __nv_bfloat16 h3 = __float2bfloat16(v.w);
            __nv_bfloat16 l0 = __float2bfloat16(v.x - __bfloat162float(h0));
            __nv_bfloat16 l1 = __float2bfloat16(v.y - __bfloat162float(h1));
            __nv_bfloat16 l2 = __float2bfloat16(v.z - __bfloat162float(h2));
            __nv_bfloat16 l3 = __float2bfloat16(v.w - __bfloat162float(h3));
            *reinterpret_cast<uint2*>(smc + BHI_B + k * 240 + n4 * 8) =
                make_uint2(pack_bf2(h0, h1), pack_bf2(h2, h3));
            *reinterpret_cast<uint2*>(smc + BLO_B + k * 240 + n4 * 8) =
                make_uint2(pack_bf2(l0, l1), pack_bf2(l2, l3));
        }
    };
    stage_b(0);
    __syncthreads();

    // ldmatrix lane offsets (bytes); A tile = 16 rows x 16 cols per ldsm_x4
    const unsigned aoff = (unsigned)((lane & 15) * 272 + (lane >> 4) * 16);
    const unsigned boff = (unsigned)(((((lane >> 3) & 1) * 8) + (lane & 7)) * 240);
    const int mg = wid & 7, hh = wid >> 3;    // 16 GEMM warps: 8 m-tiles x 2 n-halves
    const int erow = tid >> 2, eq = tid & 3;
    float ld_acc = 0.f;

    for (int c = 0; c < 8; c++) {
        {
            float acc[7][4];
            #pragma unroll
            for (int nt = 0; nt < 7; nt++)
                #pragma unroll
                for (int q = 0; q < 4; q++) acc[nt][q] = 0.f;

            const unsigned aHi0 = smem_u32 + AHI_B + (unsigned)(mg * 16) * 272u + aoff;
            const unsigned aLo0 = smem_u32 + ALO_B + (unsigned)(mg * 16) * 272u + aoff;
            const unsigned bHi0 = smem_u32 + BHI_B + (unsigned)(hh * 112) + boff;
            const unsigned bLo0 = smem_u32 + BLO_B + (unsigned)(hh * 112) + boff;

            // merged k-loop: per ks load Ahi/Alo once, apply Bhi and Blo
            #pragma unroll
            for (int ks = 0; ks < 8; ks++) {
                unsigned ah[4], al[4];
                ldsm_x4(aHi0 + (unsigned)(ks * 32), ah[0], ah[1], ah[2], ah[3]);
                ldsm_x4(aLo0 + (unsigned)(ks * 32), al[0], al[1], al[2], al[3]);
                #pragma unroll
                for (int nt = 0; nt < 7; nt++) {
                    if (hh == 1 && nt == 6) continue;      // n-tile 13: all pad
                    unsigned b0, b1, c0, c1;
                    ldsm_x2t(bHi0 + (unsigned)(ks * 3840 + nt * 16), b0, b1);
                    ldsm_x2t(bLo0 + (unsigned)(ks * 3840 + nt * 16), c0, c1);
                    mma16816(acc[nt], ah, b0, b1);   // Ahi * Bhi
                    mma16816(acc[nt], al, b0, b1);   // Alo * Bhi
                    mma16816(acc[nt], ah, c0, c1);   // Ahi * Blo
                }
            }
            // D fragments -> raw (stride 105)
            #pragma unroll
            for (int nt = 0; nt < 7; nt++) {
                int col = hh * 56 + nt * 8 + 2 * (lane & 3);
                if (col < 100) {
                    int row = mg * 16 + (lane >> 2);
                    sRaw[row * 105 + col]           = acc[nt][0];
                    sRaw[row * 105 + col + 1]       = acc[nt][1];
                    sRaw[(row + 8) * 105 + col]     = acc[nt][2];
                    sRaw[(row + 8) * 105 + col + 1] = acc[nt][3];
                }
            }
        }
        __syncthreads();

        // stage next chunk first (gmem latency hides under epilogue compute);
        // B smem reads for chunk c finished before the barrier above.
        if (c < 7) stage_b(c + 1);

        // spline epilogue (all 512 threads = 128 rows x 4 dims)
        ld_acc += rqs_epilogue(sRaw + erow * 105 + eq * 25,
                               sBP + (c * 4 + eq) * 25,
                               sXU + erow * 33 + c * 4 + eq);
        __syncthreads();
    }

    // log_det: reduce over the 4 dim-threads of each row
    ld_acc += __shfl_xor_sync(0xffffffffu, ld_acc, 1);
    ld_acc += __shfl_xor_sync(0xffffffffu, ld_acc, 2);
    if (eq == 0) out[(size_t)kB * 64 + r0 + erow] = ld_acc;

    // final y: re-read x for xm, interleave with yu; float4 coalesced
    {
        const float4* xg = reinterpret_cast<const float4*>(x + (size_t)r0 * 64);
        float4* og = reinterpret_cast<float4*>(out + (size_t)r0 * 64);
        #pragma unroll
        for (int i = tid; i < 128 * 16; i += kThreads) {
            int r = i >> 4, v = i & 15;
            float4 f = xg[i];
            og[i] = make_float4(f.x, sXU[r * 33 + 2 * v],
                                f.z, sXU[r * 33 + 2 * v + 1]);
        }
    }
}

extern "C" void kernel_launch(void* const* d_in, const int* in_sizes, int n_in,
                              void* d_out, int out_size)
{
    (void)in_sizes; (void)n_in; (void)out_size;
    const float* x   = (const float*)d_in[0];
    const float* W0  = (const float*)d_in[1];
    const float* b0  = (const float*)d_in[2];
    const float* g0  = (const float*)d_in[3];
    const float* be0 = (const float*)d_in[4];
    const float* W1  = (const float*)d_in[5];
    const float* b1  = (const float*)d_in[6];
    const float* g1  = (const float*)d_in[7];
    const float* be1 = (const float*)d_in[8];
    const float* Wp  = (const float*)d_in[9];
    const float* bp  = (const float*)d_in[10];
    float* out = (float*)d_out;

    cudaFuncSetAttribute(spline_fused_kernel,
                         cudaFuncAttributeMaxDynamicSharedMemorySize, SMEM_BYTES);
    spline_fused_kernel<<<kB / 128, kThreads, SMEM_BYTES>>>(
        x, W0, b0, g0, be0, W1, b1, g1, be1, Wp, bp, out);
}